// round 4
// baseline (speedup 1.0000x reference)
#include <cuda_runtime.h>
#include <math.h>

#define NBINS     8192
#define CAND_MAX  65536
#define N_MAX     1048576
#define EPSF      1e-8f
#define LOG_BOUND -120.0f
#define SPEC_BINS 16          /* speculative gather threshold = SPEC_BINS/NBINS */

// ---------------- device scratch (no allocations allowed) ----------------
__device__ float g_Z;            // softmax denominator (no max subtraction: s in (-2,2))
__device__ float g_sum_alloc;    // sum of allocation weighting
__device__ int   g_count;        // number of gathered candidates
__device__ int   g_thresh_bin;   // histogram threshold bin
__device__ int   g_fallback;     // 1 if speculation failed -> full regather
__device__ float g_key_norm;
__device__ int   g_hist[NBINS];
__device__ float g_e[N_MAX];     // exp(cos*beta) per row
__device__ float g_buf_u[CAND_MAX];
__device__ float g_buf_lu[CAND_MAX];
__device__ float g_buf_a[CAND_MAX];
__device__ int   g_buf_idx[CAND_MAX];

// ---------------- kernel 0: init scratch + key norm ----------------
__global__ void k_init(const float* __restrict__ key) {
    int i = blockIdx.x * blockDim.x + threadIdx.x;
    int stride = gridDim.x * blockDim.x;
    for (int b = i; b < NBINS; b += stride) g_hist[b] = 0;
    if (i == 0) {
        g_Z = 0.0f;
        g_sum_alloc = 0.0f;
        g_count = 0;
        g_fallback = 0;
        g_thresh_bin = NBINS - 1;
    }
    if (blockIdx.x == 0) {
        __shared__ float sh[64];
        if (threadIdx.x < 64) {
            float k = key[threadIdx.x];
            sh[threadIdx.x] = k * k;
        }
        __syncthreads();
        if (threadIdx.x == 0) {
            float t = 0.0f;
            for (int j = 0; j < 64; j++) t += sh[j];
            g_key_norm = sqrtf(t);
        }
    }
}

// -------- kernel 1: score stream (8 rows/warp, MLP=4 float4 loads) ---------
__global__ void k_score(const float4* __restrict__ mem4,
                        const float4* __restrict__ key4,
                        const float* __restrict__ beta_p, int N) {
    __shared__ float ssum[8];
    int lane = threadIdx.x & 31;
    int wid  = threadIdx.x >> 5;
    int gw   = blockIdx.x * 8 + wid;     // global warp id
    int sub  = lane >> 4;                // 0/1: which row of each pair
    int l16  = lane & 15;
    int r0   = gw * 8 + sub;             // rows r0, r0+2, r0+4, r0+6

    float4 k4 = key4[l16];
    float beta = beta_p[0];
    float kn = fmaxf(g_key_norm, EPSF);

    float4 m[4];
#pragma unroll
    for (int p = 0; p < 4; p++) {
        int row = r0 + 2 * p;
        m[p] = (row < N) ? mem4[(size_t)row * 16 + l16]
                         : make_float4(0.f, 0.f, 0.f, 0.f);
    }

    float esum = 0.0f;
#pragma unroll
    for (int p = 0; p < 4; p++) {
        float dot = m[p].x * k4.x + m[p].y * k4.y + m[p].z * k4.z + m[p].w * k4.w;
        float sq  = m[p].x * m[p].x + m[p].y * m[p].y + m[p].z * m[p].z + m[p].w * m[p].w;
#pragma unroll
        for (int o = 8; o; o >>= 1) {
            dot += __shfl_xor_sync(0xFFFFFFFFu, dot, o);
            sq  += __shfl_xor_sync(0xFFFFFFFFu, sq, o);
        }
        int row = r0 + 2 * p;
        if (l16 == 0 && row < N) {
            float denom = fmaxf(sqrtf(sq), EPSF) * kn;
            float e = expf((dot / denom) * beta);   // s in (-2,2): safe, no max needed
            g_e[row] = e;
            esum += e;
        }
    }
    esum += __shfl_xor_sync(0xFFFFFFFFu, esum, 16);   // merge lane0 + lane16 partials
    if (lane == 0) ssum[wid] = esum;
    __syncthreads();
    if (threadIdx.x == 0) {
        float t = 0.0f;
#pragma unroll
        for (int j = 0; j < 8; j++) t += ssum[j];
        atomicAdd(&g_Z, t);
    }
}

// -------- kernel 2: usage + histogram + speculative candidate gather -------
__global__ void k_usage(const float* __restrict__ fg,
                        const float4* __restrict__ rw4,
                        const float* __restrict__ pu,
                        const float* __restrict__ pw,
                        float* __restrict__ out_usage, int N) {
    int i = blockIdx.x * blockDim.x + threadIdx.x;
    if (i >= N) return;
    float4 r0 = rw4[i * 2];
    float4 r1 = rw4[i * 2 + 1];
    const float4* fg4 = reinterpret_cast<const float4*>(fg);
    float4 f0 = fg4[0], f1 = fg4[1];
    float ret = (1.0f - r0.x * f0.x) * (1.0f - r0.y * f0.y)
              * (1.0f - r0.z * f0.z) * (1.0f - r0.w * f0.w)
              * (1.0f - r1.x * f1.x) * (1.0f - r1.y * f1.y)
              * (1.0f - r1.z * f1.z) * (1.0f - r1.w * f1.w);
    float a = pu[i], b = pw[i];
    float u_ = (a + b - a * b) * ret;
    out_usage[i] = u_;

    int bin = (int)(u_ * (float)NBINS);
    bin = max(0, min(bin, NBINS - 1));
    atomicAdd(&g_hist[bin], 1);
    if (bin < SPEC_BINS) {
        int p = atomicAdd(&g_count, 1);
        if (p < CAND_MAX) {
            g_buf_u[p] = u_;
            g_buf_lu[p] = logf(u_);
            g_buf_idx[p] = i;
        }
    }
}

// -------- kernel 3: histogram scan -> threshold bin; validate speculation ---
__global__ void k_thresh() {
    __shared__ float spre[1024];
    int t = threadIdx.x;
    const float inv = 1.0f / (float)NBINS;
    const int BPT = NBINS / 1024;   // 8
    int base = t * BPT;
    int cnt[BPT];
    float local = 0.0f;
#pragma unroll
    for (int b = 0; b < BPT; b++) {
        cnt[b] = g_hist[base + b];
        if (cnt[b]) local += (float)cnt[b] * __logf((float)(base + b + 1) * inv);
    }
    spre[t] = local;
    __syncthreads();
    for (int o = 1; o < 1024; o <<= 1) {
        float v = (t >= o) ? spre[t - o] : 0.0f;
        __syncthreads();
        spre[t] += v;
        __syncthreads();
    }
    float prefix = (t == 0) ? 0.0f : spre[t - 1];
    if (prefix <= LOG_BOUND) {
        atomicMin(&g_thresh_bin, base);
    } else {
        float run = prefix;
#pragma unroll
        for (int b = 0; b < BPT; b++) {
            if (cnt[b]) run += (float)cnt[b] * __logf((float)(base + b + 1) * inv);
            if (run <= LOG_BOUND) {
                atomicMin(&g_thresh_bin, base + b);
                break;
            }
        }
    }
    __syncthreads();
    if (t == 0) {
        // speculation valid only if the true threshold lies inside the
        // speculatively-gathered bins and the buffer did not overflow
        if (g_thresh_bin >= SPEC_BINS || g_count > CAND_MAX) {
            g_fallback = 1;
            g_count = 0;
        }
    }
}

// -------- kernel 4: fallback regather (no-op unless speculation failed) ----
__global__ void k_gather_fb(const float* __restrict__ usage, int N) {
    if (!g_fallback) return;
    int tb = g_thresh_bin;
    int stride = gridDim.x * blockDim.x;
    for (int i = blockIdx.x * blockDim.x + threadIdx.x; i < N; i += stride) {
        float u_ = usage[i];
        int bin = (int)(u_ * (float)NBINS);
        bin = max(0, min(bin, NBINS - 1));
        if (bin <= tb) {
            int p = atomicAdd(&g_count, 1);
            if (p < CAND_MAX) {
                g_buf_u[p] = u_;
                g_buf_lu[p] = logf(u_);
                g_buf_idx[p] = i;
            }
        }
    }
}

// -------- kernel 5: allocation weighting for selected head (warp/elem) -----
__global__ void k_alloc() {
    int C = min(g_count, CAND_MAX);
    int w = (blockIdx.x * blockDim.x + threadIdx.x) >> 5;
    int lane = threadIdx.x & 31;
    if (w >= C) return;
    int tb = g_thresh_bin;
    float ui = g_buf_u[w];
    int ii = g_buf_idx[w];
    int bin = max(0, min((int)(ui * (float)NBINS), NBINS - 1));
    if (bin > tb) {                      // speculative candidate above true threshold
        if (lane == 0) g_buf_a[w] = 0.0f;   // reference alloc underflows to exact 0
        return;
    }
    float S = 0.0f;
    for (int j = lane; j < C; j += 32) {
        float uj = g_buf_u[j];
        bool before = (uj < ui) || (uj == ui && g_buf_idx[j] < ii);  // stable argsort
        if (before) S += g_buf_lu[j];
    }
#pragma unroll
    for (int o = 16; o; o >>= 1) S += __shfl_xor_sync(0xFFFFFFFFu, S, o);
    if (lane == 0) {
        float a = (1.0f - ui) * expf(S);
        g_buf_a[w] = a;
        atomicAdd(&g_sum_alloc, a);
    }
}

// -------- kernel 6: content part of ww + precedence ------------------------
__global__ void k_final(const float4* __restrict__ prec4,
                        const float* __restrict__ ag_p,
                        const float* __restrict__ wg_p,
                        float* __restrict__ out, int N, int N4) {
    int i = blockIdx.x * blockDim.x + threadIdx.x;
    if (i >= N4) return;
    float invZ = 1.0f / g_Z;
    float ag = ag_p[0];
    float wg = wg_p[0];
    float cw = wg * (1.0f - ag) * invZ;
    float sum_ww = wg * (ag * g_sum_alloc + (1.0f - ag));  // softmax sums to 1
    float oms = 1.0f - sum_ww;

    float4 e4 = reinterpret_cast<const float4*>(g_e)[i];
    float4 p4 = prec4[i];
    float4 ww, np;
    ww.x = cw * e4.x;  ww.y = cw * e4.y;  ww.z = cw * e4.z;  ww.w = cw * e4.w;
    np.x = oms * p4.x + ww.x;
    np.y = oms * p4.y + ww.y;
    np.z = oms * p4.z + ww.z;
    np.w = oms * p4.w + ww.w;
    reinterpret_cast<float4*>(out)[i] = ww;
    reinterpret_cast<float4*>(out + 2 * N)[i] = np;
}

// -------- kernel 7: scatter-add allocation contributions -------------------
__global__ void k_apply(const float* __restrict__ ag_p,
                        const float* __restrict__ wg_p,
                        float* __restrict__ out, int N) {
    int C = min(g_count, CAND_MAX);
    int w = blockIdx.x * blockDim.x + threadIdx.x;
    if (w >= C) return;
    float a = g_buf_a[w];
    if (a == 0.0f) return;
    float val = wg_p[0] * ag_p[0] * a;
    int ii = g_buf_idx[w];
    out[ii] += val;          // candidate indices unique -> no atomics
    out[2 * N + ii] += val;
}

// ---------------- launcher ----------------
extern "C" void kernel_launch(void* const* d_in, const int* in_sizes, int n_in,
                              void* d_out, int out_size) {
    const float* mem  = (const float*)d_in[0];
    const float* key  = (const float*)d_in[1];
    const float* beta = (const float*)d_in[2];
    const float* fg   = (const float*)d_in[3];
    const float* rw   = (const float*)d_in[4];
    const float* pu   = (const float*)d_in[5];
    const float* pw   = (const float*)d_in[6];
    const float* ag   = (const float*)d_in[7];
    const float* wg   = (const float*)d_in[8];
    const float* prec = (const float*)d_in[9];

    int N = in_sizes[0] / 64;   // W = 64
    int N4 = N / 4;

    float* out = (float*)d_out;
    float* out_usage = out + N; // outputs: [ww | usage | new_precedence]

    k_init<<<32, 256>>>(key);
    // 8 warps/block, 8 rows/warp -> 64 rows per block
    k_score<<<(N + 63) / 64, 256>>>(
        (const float4*)mem, (const float4*)key, beta, N);
    k_usage<<<(N + 255) / 256, 256>>>(fg, (const float4*)rw, pu, pw,
                                      out_usage, N);
    k_thresh<<<1, 1024>>>();
    k_gather_fb<<<1024, 256>>>(out_usage, N);
    k_alloc<<<CAND_MAX / 32, 1024>>>();
    k_final<<<(N4 + 255) / 256, 256>>>((const float4*)prec, ag, wg, out, N, N4);
    k_apply<<<CAND_MAX / 256, 256>>>(ag, wg, out, N);
}

// round 6
// speedup vs baseline: 2.0353x; 2.0353x over previous
#include <cuda_runtime.h>
#include <math.h>

#define NBINS    8192
#define K_MAX    16384
#define N_MAX    1048576
#define EPSF     1e-8f
#define LOG_BOUND -120.0f

// ---------------- device scratch (no allocations allowed) ----------------
__device__ unsigned int g_partial_max[1024];
__device__ float g_m;            // softmax max
__device__ float g_Z;            // softmax denominator
__device__ float g_sum_alloc;    // sum of allocation weighting
__device__ int   g_count;        // number of selected (small-usage) elements
__device__ int   g_thresh_bin;   // histogram threshold bin
__device__ float g_key_norm;
__device__ int   g_hist[NBINS];
__device__ float g_s[N_MAX];     // cosine*beta scores
__device__ float g_buf_u[K_MAX];
__device__ float g_buf_lu[K_MAX];
__device__ float g_buf_a[K_MAX];
__device__ int   g_buf_idx[K_MAX];

// orderable-uint encoding for float atomic max (handles negatives)
__device__ __forceinline__ unsigned int enc_f(float f) {
    unsigned int u = __float_as_uint(f);
    return (u & 0x80000000u) ? ~u : (u | 0x80000000u);
}
__device__ __forceinline__ float dec_f(unsigned int u) {
    return (u & 0x80000000u) ? __uint_as_float(u & 0x7FFFFFFFu)
                             : __uint_as_float(~u);
}

// ---------------- kernel 0: init scratch + key norm ----------------
__global__ void k_init(const float* __restrict__ key) {
    int i = blockIdx.x * blockDim.x + threadIdx.x;
    int stride = gridDim.x * blockDim.x;
    for (int b = i; b < NBINS; b += stride) g_hist[b] = 0;
    for (int b = i; b < 1024; b += stride) g_partial_max[b] = 0u;
    if (i == 0) {
        g_Z = 0.0f;
        g_sum_alloc = 0.0f;
        g_count = 0;
        g_thresh_bin = NBINS - 1;
    }
    if (blockIdx.x == 0) {
        __shared__ float sh[64];
        if (threadIdx.x < 64) {
            float k = key[threadIdx.x];
            sh[threadIdx.x] = k * k;
        }
        __syncthreads();
        if (threadIdx.x == 0) {
            float t = 0.0f;
            for (int j = 0; j < 64; j++) t += sh[j];
            g_key_norm = sqrtf(t);
        }
    }
}

// ---- kernel 1: main pass (4 rows per warp, 2 independent float4 loads) ----
__global__ void k_main(const float4* __restrict__ mem4,
                       const float4* __restrict__ key4,
                       const float* __restrict__ beta_p,
                       const float* __restrict__ fg,
                       const float* __restrict__ rw,
                       const float* __restrict__ pu,
                       const float* __restrict__ pw,
                       float* __restrict__ out_usage,
                       int N) {
    __shared__ unsigned int smax[8];
    int lane = threadIdx.x & 31;
    int wid  = threadIdx.x >> 5;
    if (lane == 0) smax[wid] = 0u;
    __syncthreads();

    int warp = (blockIdx.x * blockDim.x + threadIdx.x) >> 5;
    int sub  = lane >> 4;          // 0 or 1: which row of each pair
    int l16  = lane & 15;
    int rowA = warp * 4 + sub;     // pair A: rows 4w, 4w+1
    int rowB = rowA + 2;           // pair B: rows 4w+2, 4w+3
    bool actA = rowA < N;
    bool actB = rowB < N;

    float4 k4 = key4[l16];
    float4 ma = make_float4(0.f, 0.f, 0.f, 0.f);
    float4 mb = make_float4(0.f, 0.f, 0.f, 0.f);
    if (actA) ma = mem4[rowA * 16 + l16];
    if (actB) mb = mem4[rowB * 16 + l16];

    float dotA = ma.x * k4.x + ma.y * k4.y + ma.z * k4.z + ma.w * k4.w;
    float sqA  = ma.x * ma.x + ma.y * ma.y + ma.z * ma.z + ma.w * ma.w;
    float dotB = mb.x * k4.x + mb.y * k4.y + mb.z * k4.z + mb.w * k4.w;
    float sqB  = mb.x * mb.x + mb.y * mb.y + mb.z * mb.z + mb.w * mb.w;
#pragma unroll
    for (int o = 8; o; o >>= 1) {
        dotA += __shfl_xor_sync(0xFFFFFFFFu, dotA, o);
        sqA  += __shfl_xor_sync(0xFFFFFFFFu, sqA, o);
        dotB += __shfl_xor_sync(0xFFFFFFFFu, dotB, o);
        sqB  += __shfl_xor_sync(0xFFFFFFFFu, sqB, o);
    }

    // retention: lanes l16 in [0,8) of each half handle one read-head each
    int l8 = lane & 7;
    float pA = 1.0f, pB = 1.0f;
    if (l16 < 8) {
        float f = fg[l8];
        if (actA) pA = 1.0f - rw[rowA * 8 + l8] * f;
        if (actB) pB = 1.0f - rw[rowB * 8 + l8] * f;
    }
#pragma unroll
    for (int o = 4; o; o >>= 1) {
        pA *= __shfl_xor_sync(0xFFFFFFFFu, pA, o);
        pB *= __shfl_xor_sync(0xFFFFFFFFu, pB, o);
    }

    unsigned int enc = 0u;
    if (l16 == 0) {
        float beta = beta_p[0];
        float kn = fmaxf(g_key_norm, EPSF);
        if (actA) {
            float denom = fmaxf(sqrtf(sqA), EPSF) * kn;
            float s = (dotA / denom) * beta;
            g_s[rowA] = s;
            float a = pu[rowA], b = pw[rowA];
            float u_ = (a + b - a * b) * pA;
            out_usage[rowA] = u_;
            int bin = max(0, min((int)(u_ * (float)NBINS), NBINS - 1));
            atomicAdd(&g_hist[bin], 1);
            enc = enc_f(s);
        }
        if (actB) {
            float denom = fmaxf(sqrtf(sqB), EPSF) * kn;
            float s = (dotB / denom) * beta;
            g_s[rowB] = s;
            float a = pu[rowB], b = pw[rowB];
            float u_ = (a + b - a * b) * pB;
            out_usage[rowB] = u_;
            int bin = max(0, min((int)(u_ * (float)NBINS), NBINS - 1));
            atomicAdd(&g_hist[bin], 1);
            enc = max(enc, enc_f(s));
        }
    }
    // combine the row-results of this warp (lanes 0 and 16)
    enc = max(enc, __shfl_xor_sync(0xFFFFFFFFu, enc, 16));
    if (lane == 0) smax[wid] = enc;
    __syncthreads();
    if (threadIdx.x == 0) {
        unsigned int mx = 0u;
#pragma unroll
        for (int j = 0; j < 8; j++) mx = max(mx, smax[j]);
        atomicMax(&g_partial_max[blockIdx.x & 1023], mx);
    }
}

// ---------------- kernel 2: global max + threshold bin ----------------
__global__ void k_thresh() {
    __shared__ unsigned int sm[1024];
    __shared__ float spre[1024];
    int t = threadIdx.x;

    sm[t] = g_partial_max[t];
    __syncthreads();
    for (int o = 512; o; o >>= 1) {
        if (t < o) sm[t] = max(sm[t], sm[t + o]);
        __syncthreads();
    }
    if (t == 0) g_m = dec_f(sm[0]);

    // per-thread chunk of 8 bins: weighted log-upper-bound sum
    const float inv = 1.0f / (float)NBINS;
    const int BPT = NBINS / 1024;       // 8
    int base = t * BPT;
    int cnt[BPT];
    float local = 0.0f;
#pragma unroll
    for (int b = 0; b < BPT; b++) {
        cnt[b] = g_hist[base + b];
        if (cnt[b]) local += (float)cnt[b] * __logf((float)(base + b + 1) * inv);
    }
    spre[t] = local;
    __syncthreads();
    // inclusive Hillis-Steele scan
    for (int o = 1; o < 1024; o <<= 1) {
        float v = (t >= o) ? spre[t - o] : 0.0f;
        __syncthreads();
        spre[t] += v;
        __syncthreads();
    }
    float prefix = (t == 0) ? 0.0f : spre[t - 1];
    if (prefix <= LOG_BOUND) {
        atomicMin(&g_thresh_bin, base);
    } else {
        float run = prefix;
#pragma unroll
        for (int b = 0; b < BPT; b++) {
            if (cnt[b]) run += (float)cnt[b] * __logf((float)(base + b + 1) * inv);
            if (run <= LOG_BOUND) {
                atomicMin(&g_thresh_bin, base + b);
                break;
            }
        }
    }
}

// ---------------- kernel 3: softmax denominator + gather small-usage set ----
__global__ void k_gather(const float4* __restrict__ usage4, int N4) {
    __shared__ float sh[8];
    int i = blockIdx.x * blockDim.x + threadIdx.x;
    int lane = threadIdx.x & 31;
    int wid  = threadIdx.x >> 5;
    float e = 0.0f;
    float m = g_m;
    int tb = g_thresh_bin;
    if (i < N4) {
        const float4 s4 = reinterpret_cast<const float4*>(g_s)[i];
        float4 u4 = usage4[i];
        e = expf(s4.x - m) + expf(s4.y - m) + expf(s4.z - m) + expf(s4.w - m);
        float uu[4] = {u4.x, u4.y, u4.z, u4.w};
#pragma unroll
        for (int c = 0; c < 4; c++) {
            int bin = (int)(uu[c] * (float)NBINS);
            bin = max(0, min(bin, NBINS - 1));
            if (bin <= tb) {
                int p = atomicAdd(&g_count, 1);
                if (p < K_MAX) {
                    g_buf_u[p] = uu[c];
                    g_buf_lu[p] = logf(uu[c]);
                    g_buf_idx[p] = i * 4 + c;
                }
            }
        }
    }
#pragma unroll
    for (int o = 16; o; o >>= 1) e += __shfl_xor_sync(0xFFFFFFFFu, e, o);
    if (lane == 0) sh[wid] = e;
    __syncthreads();
    if (threadIdx.x == 0) {
        float t = 0.0f;
#pragma unroll
        for (int j = 0; j < 8; j++) t += sh[j];
        atomicAdd(&g_Z, t);
    }
}

// ---------------- kernel 4: allocation for selected head (warp / element) ----
__global__ void k_alloc() {
    int C = min(g_count, K_MAX);
    int w = (blockIdx.x * blockDim.x + threadIdx.x) >> 5;
    int lane = threadIdx.x & 31;
    if (w >= C) return;
    float ui = g_buf_u[w];
    int ii = g_buf_idx[w];
    float S = 0.0f;
    for (int j = lane; j < C; j += 32) {
        float uj = g_buf_u[j];
        bool before = (uj < ui) || (uj == ui && g_buf_idx[j] < ii);
        if (before) S += g_buf_lu[j];
    }
#pragma unroll
    for (int o = 16; o; o >>= 1) S += __shfl_xor_sync(0xFFFFFFFFu, S, o);
    if (lane == 0) {
        float a = (1.0f - ui) * expf(S);
        g_buf_a[w] = a;
        atomicAdd(&g_sum_alloc, a);
    }
}

// ---------------- kernel 5: finalize content part of ww + precedence --------
__global__ void k_final(const float4* __restrict__ prec4,
                        const float* __restrict__ ag_p,
                        const float* __restrict__ wg_p,
                        float* __restrict__ out, int N, int N4) {
    int i = blockIdx.x * blockDim.x + threadIdx.x;
    if (i >= N4) return;
    float invZ = 1.0f / g_Z;
    float m = g_m;
    float ag = ag_p[0];
    float wg = wg_p[0];
    float cw = wg * (1.0f - ag);
    float sum_ww = wg * (ag * g_sum_alloc + (1.0f - ag));
    float oms = 1.0f - sum_ww;

    float4 s4 = reinterpret_cast<const float4*>(g_s)[i];
    float4 p4 = prec4[i];
    float4 ww, np;
    ww.x = cw * expf(s4.x - m) * invZ;
    ww.y = cw * expf(s4.y - m) * invZ;
    ww.z = cw * expf(s4.z - m) * invZ;
    ww.w = cw * expf(s4.w - m) * invZ;
    np.x = oms * p4.x + ww.x;
    np.y = oms * p4.y + ww.y;
    np.z = oms * p4.z + ww.z;
    np.w = oms * p4.w + ww.w;
    reinterpret_cast<float4*>(out)[i] = ww;
    reinterpret_cast<float4*>(out + 2 * N)[i] = np;
}

// ---------------- kernel 6: scatter-add allocation contributions ------------
__global__ void k_apply(const float* __restrict__ ag_p,
                        const float* __restrict__ wg_p,
                        float* __restrict__ out, int N) {
    int C = min(g_count, K_MAX);
    int w = blockIdx.x * blockDim.x + threadIdx.x;
    if (w >= C) return;
    float val = wg_p[0] * ag_p[0] * g_buf_a[w];
    int ii = g_buf_idx[w];
    out[ii] += val;          // indices unique -> no atomics needed
    out[2 * N + ii] += val;
}

// ---------------- launcher ----------------
extern "C" void kernel_launch(void* const* d_in, const int* in_sizes, int n_in,
                              void* d_out, int out_size) {
    const float* mem  = (const float*)d_in[0];
    const float* key  = (const float*)d_in[1];
    const float* beta = (const float*)d_in[2];
    const float* fg   = (const float*)d_in[3];
    const float* rw   = (const float*)d_in[4];
    const float* pu   = (const float*)d_in[5];
    const float* pw   = (const float*)d_in[6];
    const float* ag   = (const float*)d_in[7];
    const float* wg   = (const float*)d_in[8];
    const float* prec = (const float*)d_in[9];

    int N = in_sizes[0] / 64;   // W = 64
    int N4 = N / 4;

    float* out = (float*)d_out;
    float* out_usage = out + N; // outputs: [ww | usage | new_precedence]

    k_init<<<64, 256>>>(key);
    // 4 rows per warp, 8 warps per block -> 32 rows/block
    k_main<<<(N + 31) / 32, 256>>>(
        (const float4*)mem, (const float4*)key, beta, fg, rw, pu, pw,
        out_usage, N);
    k_thresh<<<1, 1024>>>();
    k_gather<<<(N4 + 255) / 256, 256>>>((const float4*)out_usage, N4);
    k_alloc<<<512, 1024>>>();
    k_final<<<(N4 + 255) / 256, 256>>>((const float4*)prec, ag, wg, out, N, N4);
    k_apply<<<(K_MAX + 255) / 256, 256>>>(ag, wg, out, N);
}